// round 13
// baseline (speedup 1.0000x reference)
#include <cuda_runtime.h>
#include <cuda_bf16.h>
#include <cstdint>

#define Bb 2
#define Nn 128
#define Ll 128
#define Hh 8
#define Ee 64

// smem: six bf16 tiles (Q/K/V x hi/lo), 128 rows x 64 cols, pitch 144B
// (36 banks ≡ 4 mod 32 -> conflict-free ldmatrix). V has its OWN region:
// no aliasing -> no barrier between Q-frag reads and V stores.
#define QP 144
#define SQ_H 0
#define SQ_L 18432
#define SK_H 36864
#define SK_L 55296
#define SV_H 73728
#define SV_L 92160
#define SM_TOTAL 110592

// V_t stored packed: per element u32 = bf16_hi | bf16_lo<<16
__device__ uint32_t g_vt[(size_t)Bb * Nn * Ll * Hh * Ee];

// ---------------- helpers ----------------
__device__ __forceinline__ uint32_t smem_u32(const void* p) {
    uint32_t a;
    asm("{ .reg .u64 t; cvta.to.shared.u64 t, %1; cvt.u32.u64 %0, t; }"
        : "=r"(a) : "l"(p));
    return a;
}
__device__ __forceinline__ void ldsm4(uint32_t* r, uint32_t a) {
    asm volatile("ldmatrix.sync.aligned.m8n8.x4.shared.b16 {%0,%1,%2,%3}, [%4];"
                 : "=r"(r[0]), "=r"(r[1]), "=r"(r[2]), "=r"(r[3]) : "r"(a));
}
__device__ __forceinline__ void ldsm4t(uint32_t* r, uint32_t a) {
    asm volatile("ldmatrix.sync.aligned.m8n8.x4.trans.shared.b16 {%0,%1,%2,%3}, [%4];"
                 : "=r"(r[0]), "=r"(r[1]), "=r"(r[2]), "=r"(r[3]) : "r"(a));
}
__device__ __forceinline__ void mma16816(float* c, const uint32_t* a, const uint32_t* b) {
    asm volatile(
        "mma.sync.aligned.m16n8k16.row.col.f32.bf16.bf16.f32 "
        "{%0,%1,%2,%3}, {%4,%5,%6,%7}, {%8,%9}, {%0,%1,%2,%3};"
        : "+f"(c[0]), "+f"(c[1]), "+f"(c[2]), "+f"(c[3])
        : "r"(a[0]), "r"(a[1]), "r"(a[2]), "r"(a[3]), "r"(b[0]), "r"(b[1]));
}
__device__ __forceinline__ uint32_t cvt_bf16x2(float y, float x) {
    uint32_t r;
    asm("cvt.rn.bf16x2.f32 %0, %1, %2;" : "=r"(r) : "f"(y), "f"(x));
    return r;
}
// hi = truncated-bf16 pair (PRMT), lo = rn-bf16 of exact residuals
__device__ __forceinline__ void split_pair(float x, float y, uint32_t& hi, uint32_t& lo) {
    const uint32_t u0 = __float_as_uint(x), u1 = __float_as_uint(y);
    hi = __byte_perm(u0, u1, 0x7632);
    const float l0 = x - __uint_as_float(u0 & 0xFFFF0000u);
    const float l1 = y - __uint_as_float(u1 & 0xFFFF0000u);
    lo = cvt_bf16x2(l1, l0);
}

// ---- MMA1 half: 8 n-tiles (64 S-columns) into c[8][4] ----
__device__ __forceinline__ void mma1_half(float c[8][4], uint32_t kb,
                                          const uint32_t qah[4][4],
                                          const uint32_t qal[4][4]) {
#pragma unroll
    for (int nt = 0; nt < 8; nt += 2) {
        const uint32_t brh = kb + (uint32_t)(nt * 8 * QP);
        uint32_t b0[4], b1[4], d0[4], d1[4];
        ldsm4(b0, brh); ldsm4(b1, brh + 64);
        ldsm4(d0, brh + 8 * QP); ldsm4(d1, brh + 8 * QP + 64);
        // Qh*Kh
        mma16816(c[nt], qah[0], b0);     mma16816(c[nt + 1], qah[0], d0);
        mma16816(c[nt], qah[1], b0 + 2); mma16816(c[nt + 1], qah[1], d0 + 2);
        mma16816(c[nt], qah[2], b1);     mma16816(c[nt + 1], qah[2], d1);
        mma16816(c[nt], qah[3], b1 + 2); mma16816(c[nt + 1], qah[3], d1 + 2);
        // Ql*Kh
        mma16816(c[nt], qal[0], b0);     mma16816(c[nt + 1], qal[0], d0);
        mma16816(c[nt], qal[1], b0 + 2); mma16816(c[nt + 1], qal[1], d0 + 2);
        mma16816(c[nt], qal[2], b1);     mma16816(c[nt + 1], qal[2], d1);
        mma16816(c[nt], qal[3], b1 + 2); mma16816(c[nt + 1], qal[3], d1 + 2);
        // Kl fragments (reuse regs)
        const uint32_t brl = brh + (SK_L - SK_H);
        ldsm4(b0, brl); ldsm4(b1, brl + 64);
        ldsm4(d0, brl + 8 * QP); ldsm4(d1, brl + 8 * QP + 64);
        // Qh*Kl
        mma16816(c[nt], qah[0], b0);     mma16816(c[nt + 1], qah[0], d0);
        mma16816(c[nt], qah[1], b0 + 2); mma16816(c[nt + 1], qah[1], d0 + 2);
        mma16816(c[nt], qah[2], b1);     mma16816(c[nt + 1], qah[2], d1);
        mma16816(c[nt], qah[3], b1 + 2); mma16816(c[nt + 1], qah[3], d1 + 2);
    }
}

// ---- MMA2 half: o += P_half (16x64) * V rows [hb*64, hb*64+64) ----
__device__ __forceinline__ void mma2_half(float o[8][4], uint32_t vb,
                                          const uint32_t* ph, const uint32_t* pl) {
#pragma unroll
    for (int ks = 0; ks < 4; ks++) {
        const uint32_t* a_h = ph + ks * 4;
        const uint32_t* a_l = pl + ks * 4;
        const uint32_t bh0 = vb + (uint32_t)(ks * 16 * QP);
        const uint32_t bl0 = bh0 + (SV_L - SV_H);
#pragma unroll
        for (int p = 0; p < 4; p++) {
            uint32_t bb[4];
            ldsm4t(bb, bh0 + p * 32);
            mma16816(o[2 * p],     a_h, bb);
            mma16816(o[2 * p + 1], a_h, bb + 2);
            mma16816(o[2 * p],     a_l, bb);
            mma16816(o[2 * p + 1], a_l, bb + 2);
        }
#pragma unroll
        for (int p = 0; p < 4; p++) {
            uint32_t bb[4];
            ldsm4t(bb, bl0 + p * 32);
            mma16816(o[2 * p],     a_h, bb);
            mma16816(o[2 * p + 1], a_h, bb + 2);
        }
    }
}

// ---------------------------------------------------------------------------
template <bool SPATIAL>
__global__ __launch_bounds__(256, 2)
void attn_mma_kernel(const float* __restrict__ q, const float* __restrict__ k,
                     const float* __restrict__ v32, const uint32_t* __restrict__ vpk,
                     const float* __restrict__ mask,
                     uint32_t* __restrict__ dst_pk, float* __restrict__ dst_f)
{
    extern __shared__ char sm[];
    const uint32_t sb = smem_u32(sm);
    const int t = threadIdx.x, lane = t & 31, wid = t >> 5;

    const int pid = blockIdx.x;
    const int h = pid & 7;
    const int rl = (pid >> 3) & 127;
    const int b = pid >> 10;
    int base, rstride;
    if (SPATIAL) { base = (b * Nn * Ll + rl) * (Hh * Ee) + h * Ee; rstride = Ll * Hh * Ee; }
    else         { base = ((b * Nn + rl) * Ll) * (Hh * Ee) + h * Ee; rstride = Hh * Ee; }

    // Q pre-scaled by softmax_scale * log2(e): exp(0.125 s) == exp2(QS s)
    const float QS = 0.125f * 1.44269504088896f;

    // ---- load + convert Q (scaled), K ----
#pragma unroll
    for (int i = 0; i < 8; i++) {
        const int idx = i * 256 + t;
        const int row = idx >> 4, e4 = idx & 15;
        const int go = base + row * rstride + e4 * 4;
        float4 qv = *(const float4*)(q + go);
        const float4 kv = *(const float4*)(k + go);
        qv.x *= QS; qv.y *= QS; qv.z *= QS; qv.w *= QS;
        const uint32_t off = (uint32_t)(row * QP + e4 * 8);
        uint32_t h0, l0, h1, l1;
        split_pair(qv.x, qv.y, h0, l0); split_pair(qv.z, qv.w, h1, l1);
        *(uint2*)(sm + SQ_H + off) = make_uint2(h0, h1);
        *(uint2*)(sm + SQ_L + off) = make_uint2(l0, l1);
        split_pair(kv.x, kv.y, h0, l0); split_pair(kv.z, kv.w, h1, l1);
        *(uint2*)(sm + SK_H + off) = make_uint2(h0, h1);
        *(uint2*)(sm + SK_L + off) = make_uint2(l0, l1);
    }
    __syncthreads();                        // sync1: Q/K tiles visible

    // ---- Q A-fragments (hi+lo) into registers ----
    const int r0 = wid * 16;
    uint32_t qah[4][4], qal[4][4];
    {
        const uint32_t arow_h = sb + SQ_H
            + (uint32_t)((r0 + (lane & 15)) * QP + (lane >> 4) * 16);
        const uint32_t arow_l = arow_h + (SQ_L - SQ_H);
#pragma unroll
        for (int ks = 0; ks < 4; ks++) {
            ldsm4(qah[ks], arow_h + ks * 32);
            ldsm4(qal[ks], arow_l + ks * 32);
        }
    }
    // NO barrier here: V has its own smem region, no aliasing hazard.

    // ---- TEMPORAL: V load+convert now (hides under both MMA1 halves) ----
    if (!SPATIAL) {
#pragma unroll
        for (int i = 0; i < 8; i++) {
            const int idx = i * 256 + t;
            const int row = idx >> 4, e4 = idx & 15;
            const uint32_t off = (uint32_t)(row * QP + e4 * 8);
            const int go = base + row * rstride + e4 * 4;
            const float4 vv = *(const float4*)(v32 + go);
            uint32_t h0, l0, h1, l1;
            split_pair(vv.x, vv.y, h0, l0); split_pair(vv.z, vv.w, h1, l1);
            *(uint2*)(sm + SV_H + off) = make_uint2(h0, h1);
            *(uint2*)(sm + SV_L + off) = make_uint2(l0, l1);
        }
    }

    const int row_lo = r0 + (lane >> 2);
    const int row_hi = row_lo + 8;
    const float* mrow_lo = SPATIAL ? mask + ((size_t)b * Nn + row_lo) * Nn : nullptr;
    const float* mrow_hi = SPATIAL ? mask + ((size_t)b * Nn + row_hi) * Nn : nullptr;
    const int mcol = (lane & 3) * 2;
    const uint32_t kbase = sb + SK_H
        + (uint32_t)((lane & 7) * QP + ((lane >> 3) & 3) * 16);
    const uint32_t vbase = sb + SV_H
        + (uint32_t)(((lane & 7) + ((lane >> 3) & 1) * 8) * QP + ((lane >> 4) & 1) * 16);

    float slo = 0.f, shi = 0.f;
    uint32_t p1h[16], p1l[16], p2h[16], p2l[16];

    // ---- MMA1 half 1 (S columns 0..63) ----
    float c[8][4];
#pragma unroll
    for (int nt = 0; nt < 8; nt++)
#pragma unroll
        for (int j = 0; j < 4; j++) c[nt][j] = 0.f;
    mma1_half(c, kbase, qah, qal);

    // ---- mask + exp + convert half 1 (MUFU latency drains under MMA1 h2) ----
#pragma unroll
    for (int nt = 0; nt < 8; nt++) {
        if (SPATIAL) {
            const int col = nt * 8 + mcol;
            const float2 ml = *(const float2*)(mrow_lo + col);
            const float2 mh = *(const float2*)(mrow_hi + col);
            c[nt][0] *= ml.x; c[nt][1] *= ml.y;
            c[nt][2] *= mh.x; c[nt][3] *= mh.y;
        }
        const float e0 = exp2f(c[nt][0]);
        const float e1 = exp2f(c[nt][1]);
        const float e2 = exp2f(c[nt][2]);
        const float e3 = exp2f(c[nt][3]);
        slo += e0 + e1;
        shi += e2 + e3;
        const int s = (nt >> 1) * 4 + (nt & 1) * 2;
        split_pair(e0, e1, p1h[s + 0], p1l[s + 0]);
        split_pair(e2, e3, p1h[s + 1], p1l[s + 1]);
    }

    // ---- SPATIAL: V load here — warps staggered by conv h1, and MMA1 h2
    //      (~1500 cyc) follows within-warp to drain the LDG->PRMT->STS chain
    //      before sync3 ----
    if (SPATIAL) {
#pragma unroll
        for (int i = 0; i < 8; i++) {
            const int idx = i * 256 + t;
            const int row = idx >> 4, e4 = idx & 15;
            const uint32_t off = (uint32_t)(row * QP + e4 * 8);
            const int go = base + row * rstride + e4 * 4;
            const uint4 w = *(const uint4*)(vpk + go);
            *(uint2*)(sm + SV_H + off) = make_uint2(__byte_perm(w.x, w.y, 0x5410),
                                                   __byte_perm(w.z, w.w, 0x5410));
            *(uint2*)(sm + SV_L + off) = make_uint2(__byte_perm(w.x, w.y, 0x7632),
                                                   __byte_perm(w.z, w.w, 0x7632));
        }
    }

    // ---- MMA1 half 2 (S columns 64..127) ----
#pragma unroll
    for (int nt = 0; nt < 8; nt++)
#pragma unroll
        for (int j = 0; j < 4; j++) c[nt][j] = 0.f;
    mma1_half(c, kbase + (uint32_t)(64 * QP), qah, qal);

    __syncthreads();                        // sync2: V tiles ready everywhere

    // ---- MMA2 half 1 ----
    float o[8][4];
#pragma unroll
    for (int nt = 0; nt < 8; nt++)
#pragma unroll
        for (int j = 0; j < 4; j++) o[nt][j] = 0.f;
    mma2_half(o, vbase, p1h, p1l);

    // ---- mask + exp + convert half 2 (drains under other warps' MMA2) ----
#pragma unroll
    for (int nt = 0; nt < 8; nt++) {
        if (SPATIAL) {
            const int col = 64 + nt * 8 + mcol;
            const float2 ml = *(const float2*)(mrow_lo + col);
            const float2 mh = *(const float2*)(mrow_hi + col);
            c[nt][0] *= ml.x; c[nt][1] *= ml.y;
            c[nt][2] *= mh.x; c[nt][3] *= mh.y;
        }
        const float e0 = exp2f(c[nt][0]);
        const float e1 = exp2f(c[nt][1]);
        const float e2 = exp2f(c[nt][2]);
        const float e3 = exp2f(c[nt][3]);
        slo += e0 + e1;
        shi += e2 + e3;
        const int s = (nt >> 1) * 4 + (nt & 1) * 2;
        split_pair(e0, e1, p2h[s + 0], p2l[s + 0]);
        split_pair(e2, e3, p2h[s + 1], p2l[s + 1]);
    }

    // ---- MMA2 half 2 ----
    mma2_half(o, vbase + (uint32_t)(64 * QP), p2h, p2l);

    // ---- deferred softmax reduction ----
    slo += __shfl_xor_sync(0xFFFFFFFF, slo, 1);
    slo += __shfl_xor_sync(0xFFFFFFFF, slo, 2);
    shi += __shfl_xor_sync(0xFFFFFFFF, shi, 1);
    shi += __shfl_xor_sync(0xFFFFFFFF, shi, 2);
    const float invlo = 1.0f / slo, invhi = 1.0f / shi;

    // ---- epilogue ----
    if (SPATIAL) {
        float* orow_lo = dst_f + base + row_lo * rstride;
        float* orow_hi = dst_f + base + row_hi * rstride;
#pragma unroll
        for (int nt = 0; nt < 8; nt++) {
            const int col = nt * 8 + mcol;
            *(float2*)(orow_lo + col) = make_float2(o[nt][0] * invlo, o[nt][1] * invlo);
            *(float2*)(orow_hi + col) = make_float2(o[nt][2] * invhi, o[nt][3] * invhi);
        }
    } else {
        uint32_t* orow_lo = dst_pk + base + row_lo * rstride;
        uint32_t* orow_hi = dst_pk + base + row_hi * rstride;
#pragma unroll
        for (int nt = 0; nt < 8; nt++) {
            const int col = nt * 8 + mcol;
            {
                const float f0 = o[nt][0] * invlo, f1 = o[nt][1] * invlo;
                const uint32_t u0 = __float_as_uint(f0), u1 = __float_as_uint(f1);
                const float l0 = f0 - __uint_as_float(u0 & 0xFFFF0000u);
                const float l1 = f1 - __uint_as_float(u1 & 0xFFFF0000u);
                const uint32_t lop = cvt_bf16x2(l1, l0);
                uint2 w;
                w.x = __byte_perm(u0, lop, 0x5432);
                w.y = __byte_perm(u1, lop, 0x7632);
                *(uint2*)(orow_lo + col) = w;
            }
            {
                const float f0 = o[nt][2] * invhi, f1 = o[nt][3] * invhi;
                const uint32_t u0 = __float_as_uint(f0), u1 = __float_as_uint(f1);
                const float l0 = f0 - __uint_as_float(u0 & 0xFFFF0000u);
                const float l1 = f1 - __uint_as_float(u1 & 0xFFFF0000u);
                const uint32_t lop = cvt_bf16x2(l1, l0);
                uint2 w;
                w.x = __byte_perm(u0, lop, 0x5432);
                w.y = __byte_perm(u1, lop, 0x7632);
                *(uint2*)(orow_hi + col) = w;
            }
        }
    }
}

// ---------------------------------------------------------------------------
extern "C" void kernel_launch(void* const* d_in, const int* in_sizes, int n_in,
                              void* d_out, int out_size)
{
    const float* q    = (const float*)d_in[0];
    const float* k    = (const float*)d_in[1];
    const float* v    = (const float*)d_in[2];
    const float* mask = (const float*)d_in[3];
    float* out = (float*)d_out;

    uint32_t* vt;
    cudaGetSymbolAddress((void**)&vt, g_vt);

    cudaFuncSetAttribute(attn_mma_kernel<false>,
                         cudaFuncAttributeMaxDynamicSharedMemorySize, SM_TOTAL);
    cudaFuncSetAttribute(attn_mma_kernel<true>,
                         cudaFuncAttributeMaxDynamicSharedMemorySize, SM_TOTAL);

    attn_mma_kernel<false><<<Bb * Nn * Hh, 256, SM_TOTAL>>>(
        q, k, v, nullptr, nullptr, vt, nullptr);
    attn_mma_kernel<true><<<Bb * Ll * Hh, 256, SM_TOTAL>>>(
        q, k, nullptr, (const uint32_t*)vt, mask, nullptr, out);
}

// round 14
// speedup vs baseline: 1.6815x; 1.6815x over previous
#include <cuda_runtime.h>
#include <cuda_bf16.h>
#include <cstdint>

#define Bb 2
#define Nn 128
#define Ll 128
#define Hh 8
#define Ee 64

// smem: Q/K bf16 hi/lo tiles, 128 rows x 64 cols, pitch 144B (36 banks ≡ 4 mod 32
// -> conflict-free ldmatrix). V hi/lo overwrites the Q region once Q frags are in regs.
#define QP 144
#define SQ_H 0
#define SQ_L 18432
#define SK_H 36864
#define SK_L 55296
#define SM_TOTAL 73728
#define SV_H 0
#define SV_L 18432

// V_t stored packed: per element u32 = bf16_hi | bf16_lo<<16
__device__ uint32_t g_vt[(size_t)Bb * Nn * Ll * Hh * Ee];

// ---------------- helpers ----------------
__device__ __forceinline__ uint32_t smem_u32(const void* p) {
    uint32_t a;
    asm("{ .reg .u64 t; cvta.to.shared.u64 t, %1; cvt.u32.u64 %0, t; }"
        : "=r"(a) : "l"(p));
    return a;
}
__device__ __forceinline__ void ldsm4(uint32_t* r, uint32_t a) {
    asm volatile("ldmatrix.sync.aligned.m8n8.x4.shared.b16 {%0,%1,%2,%3}, [%4];"
                 : "=r"(r[0]), "=r"(r[1]), "=r"(r[2]), "=r"(r[3]) : "r"(a));
}
__device__ __forceinline__ void ldsm4t(uint32_t* r, uint32_t a) {
    asm volatile("ldmatrix.sync.aligned.m8n8.x4.trans.shared.b16 {%0,%1,%2,%3}, [%4];"
                 : "=r"(r[0]), "=r"(r[1]), "=r"(r[2]), "=r"(r[3]) : "r"(a));
}
__device__ __forceinline__ void mma16816(float* c, const uint32_t* a, const uint32_t* b) {
    asm volatile(
        "mma.sync.aligned.m16n8k16.row.col.f32.bf16.bf16.f32 "
        "{%0,%1,%2,%3}, {%4,%5,%6,%7}, {%8,%9}, {%0,%1,%2,%3};"
        : "+f"(c[0]), "+f"(c[1]), "+f"(c[2]), "+f"(c[3])
        : "r"(a[0]), "r"(a[1]), "r"(a[2]), "r"(a[3]), "r"(b[0]), "r"(b[1]));
}
__device__ __forceinline__ uint32_t cvt_bf16x2(float y, float x) {
    uint32_t r;
    asm("cvt.rn.bf16x2.f32 %0, %1, %2;" : "=r"(r) : "f"(y), "f"(x));
    return r;
}
// hi = truncated-bf16 pair (PRMT), lo = rn-bf16 of exact residuals
__device__ __forceinline__ void split_pair(float x, float y, uint32_t& hi, uint32_t& lo) {
    const uint32_t u0 = __float_as_uint(x), u1 = __float_as_uint(y);
    hi = __byte_perm(u0, u1, 0x7632);
    const float l0 = x - __uint_as_float(u0 & 0xFFFF0000u);
    const float l1 = y - __uint_as_float(u1 & 0xFFFF0000u);
    lo = cvt_bf16x2(l1, l0);
}

// ---- MMA1 half: 8 n-tiles (64 S-columns) into c[8][4] ----
__device__ __forceinline__ void mma1_half(float c[8][4], uint32_t kb,
                                          const uint32_t qah[4][4],
                                          const uint32_t qal[4][4]) {
#pragma unroll
    for (int nt = 0; nt < 8; nt += 2) {
        const uint32_t brh = kb + (uint32_t)(nt * 8 * QP);
        uint32_t b0[4], b1[4], d0[4], d1[4];
        ldsm4(b0, brh); ldsm4(b1, brh + 64);
        ldsm4(d0, brh + 8 * QP); ldsm4(d1, brh + 8 * QP + 64);
        // Qh*Kh
        mma16816(c[nt], qah[0], b0);     mma16816(c[nt + 1], qah[0], d0);
        mma16816(c[nt], qah[1], b0 + 2); mma16816(c[nt + 1], qah[1], d0 + 2);
        mma16816(c[nt], qah[2], b1);     mma16816(c[nt + 1], qah[2], d1);
        mma16816(c[nt], qah[3], b1 + 2); mma16816(c[nt + 1], qah[3], d1 + 2);
        // Ql*Kh
        mma16816(c[nt], qal[0], b0);     mma16816(c[nt + 1], qal[0], d0);
        mma16816(c[nt], qal[1], b0 + 2); mma16816(c[nt + 1], qal[1], d0 + 2);
        mma16816(c[nt], qal[2], b1);     mma16816(c[nt + 1], qal[2], d1);
        mma16816(c[nt], qal[3], b1 + 2); mma16816(c[nt + 1], qal[3], d1 + 2);
        // Kl fragments (reuse regs)
        const uint32_t brl = brh + (SK_L - SK_H);
        ldsm4(b0, brl); ldsm4(b1, brl + 64);
        ldsm4(d0, brl + 8 * QP); ldsm4(d1, brl + 8 * QP + 64);
        // Qh*Kl
        mma16816(c[nt], qah[0], b0);     mma16816(c[nt + 1], qah[0], d0);
        mma16816(c[nt], qah[1], b0 + 2); mma16816(c[nt + 1], qah[1], d0 + 2);
        mma16816(c[nt], qah[2], b1);     mma16816(c[nt + 1], qah[2], d1);
        mma16816(c[nt], qah[3], b1 + 2); mma16816(c[nt + 1], qah[3], d1 + 2);
    }
}

// ---- MMA2 half: o += P_half (16x64) * V rows [hb*64, hb*64+64) ----
__device__ __forceinline__ void mma2_half(float o[8][4], uint32_t vb,
                                          const uint32_t* ph, const uint32_t* pl) {
#pragma unroll
    for (int ks = 0; ks < 4; ks++) {
        const uint32_t* a_h = ph + ks * 4;
        const uint32_t* a_l = pl + ks * 4;
        const uint32_t bh0 = vb + (uint32_t)(ks * 16 * QP);
        const uint32_t bl0 = bh0 + (SV_L - SV_H);
#pragma unroll
        for (int p = 0; p < 4; p++) {
            uint32_t bb[4];
            ldsm4t(bb, bh0 + p * 32);
            mma16816(o[2 * p],     a_h, bb);
            mma16816(o[2 * p + 1], a_h, bb + 2);
            mma16816(o[2 * p],     a_l, bb);
            mma16816(o[2 * p + 1], a_l, bb + 2);
        }
#pragma unroll
        for (int p = 0; p < 4; p++) {
            uint32_t bb[4];
            ldsm4t(bb, bl0 + p * 32);
            mma16816(o[2 * p],     a_h, bb);
            mma16816(o[2 * p + 1], a_h, bb + 2);
        }
    }
}

// ---------------------------------------------------------------------------
template <bool SPATIAL>
__global__ __launch_bounds__(256, 2)
void attn_mma_kernel(const float* __restrict__ q, const float* __restrict__ k,
                     const float* __restrict__ v32, const uint32_t* __restrict__ vpk,
                     const float* __restrict__ mask,
                     uint32_t* __restrict__ dst_pk, float* __restrict__ dst_f)
{
    extern __shared__ char sm[];
    const uint32_t sb = smem_u32(sm);
    const int t = threadIdx.x, lane = t & 31, wid = t >> 5;

    const int pid = blockIdx.x;
    const int h = pid & 7;
    const int rl = (pid >> 3) & 127;
    const int b = pid >> 10;
    int base, rstride;
    if (SPATIAL) { base = (b * Nn * Ll + rl) * (Hh * Ee) + h * Ee; rstride = Ll * Hh * Ee; }
    else         { base = ((b * Nn + rl) * Ll) * (Hh * Ee) + h * Ee; rstride = Hh * Ee; }

    // Q pre-scaled by softmax_scale * log2(e): exp(0.125 s) == exp2(QS s)
    const float QS = 0.125f * 1.44269504088896f;

    // ---- load + convert Q (scaled), K ----
#pragma unroll
    for (int i = 0; i < 8; i++) {
        const int idx = i * 256 + t;
        const int row = idx >> 4, e4 = idx & 15;
        const int go = base + row * rstride + e4 * 4;
        float4 qv = *(const float4*)(q + go);
        const float4 kv = *(const float4*)(k + go);
        qv.x *= QS; qv.y *= QS; qv.z *= QS; qv.w *= QS;
        const uint32_t off = (uint32_t)(row * QP + e4 * 8);
        uint32_t h0, l0, h1, l1;
        split_pair(qv.x, qv.y, h0, l0); split_pair(qv.z, qv.w, h1, l1);
        *(uint2*)(sm + SQ_H + off) = make_uint2(h0, h1);
        *(uint2*)(sm + SQ_L + off) = make_uint2(l0, l1);
        split_pair(kv.x, kv.y, h0, l0); split_pair(kv.z, kv.w, h1, l1);
        *(uint2*)(sm + SK_H + off) = make_uint2(h0, h1);
        *(uint2*)(sm + SK_L + off) = make_uint2(l0, l1);
    }
    __syncthreads();                        // sync1: Q/K tiles visible

    // ---- Q A-fragments (hi+lo) into registers; then Q smem region is dead ----
    const int r0 = wid * 16;
    uint32_t qah[4][4], qal[4][4];
    {
        const uint32_t arow_h = sb + SQ_H
            + (uint32_t)((r0 + (lane & 15)) * QP + (lane >> 4) * 16);
        const uint32_t arow_l = arow_h + (SQ_L - SQ_H);
#pragma unroll
        for (int ks = 0; ks < 4; ks++) {
            ldsm4(qah[ks], arow_h + ks * 32);
            ldsm4(qal[ks], arow_l + ks * 32);
        }
    }
    __syncthreads();                        // sync2: all warps hold Q frags

    // ---- TEMPORAL: V load+convert here (hides under both MMA1 halves) ----
    if (!SPATIAL) {
#pragma unroll
        for (int i = 0; i < 8; i++) {
            const int idx = i * 256 + t;
            const int row = idx >> 4, e4 = idx & 15;
            const uint32_t off = (uint32_t)(row * QP + e4 * 8);
            const int go = base + row * rstride + e4 * 4;
            const float4 vv = *(const float4*)(v32 + go);
            uint32_t h0, l0, h1, l1;
            split_pair(vv.x, vv.y, h0, l0); split_pair(vv.z, vv.w, h1, l1);
            *(uint2*)(sm + SV_H + off) = make_uint2(h0, h1);
            *(uint2*)(sm + SV_L + off) = make_uint2(l0, l1);
        }
    }

    const int row_lo = r0 + (lane >> 2);
    const int row_hi = row_lo + 8;
    const float* mrow_lo = SPATIAL ? mask + ((size_t)b * Nn + row_lo) * Nn : nullptr;
    const float* mrow_hi = SPATIAL ? mask + ((size_t)b * Nn + row_hi) * Nn : nullptr;
    const int mcol = (lane & 3) * 2;
    const uint32_t kbase = sb + SK_H
        + (uint32_t)((lane & 7) * QP + ((lane >> 3) & 3) * 16);
    const uint32_t vbase = sb + SV_H
        + (uint32_t)(((lane & 7) + ((lane >> 3) & 1) * 8) * QP + ((lane >> 4) & 1) * 16);

    float slo = 0.f, shi = 0.f;
    uint32_t p1h[16], p1l[16], p2h[16], p2l[16];

    // ---- MMA1 half 1 (S columns 0..63) ----
    float c[8][4];
#pragma unroll
    for (int nt = 0; nt < 8; nt++)
#pragma unroll
        for (int j = 0; j < 4; j++) c[nt][j] = 0.f;
    mma1_half(c, kbase, qah, qal);

    // ---- mask + exp + convert half 1 (MUFU latency drains under MMA1 h2) ----
#pragma unroll
    for (int nt = 0; nt < 8; nt++) {
        if (SPATIAL) {
            const int col = nt * 8 + mcol;
            const float2 ml = *(const float2*)(mrow_lo + col);
            const float2 mh = *(const float2*)(mrow_hi + col);
            c[nt][0] *= ml.x; c[nt][1] *= ml.y;
            c[nt][2] *= mh.x; c[nt][3] *= mh.y;
        }
        const float e0 = exp2f(c[nt][0]);
        const float e1 = exp2f(c[nt][1]);
        const float e2 = exp2f(c[nt][2]);
        const float e3 = exp2f(c[nt][3]);
        slo += e0 + e1;
        shi += e2 + e3;
        const int s = (nt >> 1) * 4 + (nt & 1) * 2;
        split_pair(e0, e1, p1h[s + 0], p1l[s + 0]);
        split_pair(e2, e3, p1h[s + 1], p1l[s + 1]);
    }

    // ---- SPATIAL: V load here — after conv h1 (warps staggered), with the
    //      full MMA1 h2 burst (~1500 cyc) following within-warp to drain the
    //      LDG->PRMT->STS chain before sync3. (Sole diff vs R12.) ----
    if (SPATIAL) {
#pragma unroll
        for (int i = 0; i < 8; i++) {
            const int idx = i * 256 + t;
            const int row = idx >> 4, e4 = idx & 15;
            const uint32_t off = (uint32_t)(row * QP + e4 * 8);
            const int go = base + row * rstride + e4 * 4;
            const uint4 w = *(const uint4*)(vpk + go);
            *(uint2*)(sm + SV_H + off) = make_uint2(__byte_perm(w.x, w.y, 0x5410),
                                                   __byte_perm(w.z, w.w, 0x5410));
            *(uint2*)(sm + SV_L + off) = make_uint2(__byte_perm(w.x, w.y, 0x7632),
                                                   __byte_perm(w.z, w.w, 0x7632));
        }
    }

    // ---- MMA1 half 2 (S columns 64..127) ----
#pragma unroll
    for (int nt = 0; nt < 8; nt++)
#pragma unroll
        for (int j = 0; j < 4; j++) c[nt][j] = 0.f;
    mma1_half(c, kbase + (uint32_t)(64 * QP), qah, qal);

    __syncthreads();                        // sync3: V tiles ready everywhere

    // ---- MMA2 half 1 ----
    float o[8][4];
#pragma unroll
    for (int nt = 0; nt < 8; nt++)
#pragma unroll
        for (int j = 0; j < 4; j++) o[nt][j] = 0.f;
    mma2_half(o, vbase, p1h, p1l);

    // ---- mask + exp + convert half 2 (drains under other warps' MMA2) ----
#pragma unroll
    for (int nt = 0; nt < 8; nt++) {
        if (SPATIAL) {
            const int col = 64 + nt * 8 + mcol;
            const float2 ml = *(const float2*)(mrow_lo + col);
            const float2 mh = *(const float2*)(mrow_hi + col);
            c[nt][0] *= ml.x; c[nt][1] *= ml.y;
            c[nt][2] *= mh.x; c[nt][3] *= mh.y;
        }
        const float e0 = exp2f(c[nt][0]);
        const float e1 = exp2f(c[nt][1]);
        const float e2 = exp2f(c[nt][2]);
        const float e3 = exp2f(c[nt][3]);
        slo += e0 + e1;
        shi += e2 + e3;
        const int s = (nt >> 1) * 4 + (nt & 1) * 2;
        split_pair(e0, e1, p2h[s + 0], p2l[s + 0]);
        split_pair(e2, e3, p2h[s + 1], p2l[s + 1]);
    }

    // ---- MMA2 half 2 ----
    mma2_half(o, vbase + (uint32_t)(64 * QP), p2h, p2l);

    // ---- deferred softmax reduction ----
    slo += __shfl_xor_sync(0xFFFFFFFF, slo, 1);
    slo += __shfl_xor_sync(0xFFFFFFFF, slo, 2);
    shi += __shfl_xor_sync(0xFFFFFFFF, shi, 1);
    shi += __shfl_xor_sync(0xFFFFFFFF, shi, 2);
    const float invlo = 1.0f / slo, invhi = 1.0f / shi;

    // ---- epilogue ----
    if (SPATIAL) {
        float* orow_lo = dst_f + base + row_lo * rstride;
        float* orow_hi = dst_f + base + row_hi * rstride;
#pragma unroll
        for (int nt = 0; nt < 8; nt++) {
            const int col = nt * 8 + mcol;
            *(float2*)(orow_lo + col) = make_float2(o[nt][0] * invlo, o[nt][1] * invlo);
            *(float2*)(orow_hi + col) = make_float2(o[nt][2] * invhi, o[nt][3] * invhi);
        }
    } else {
        uint32_t* orow_lo = dst_pk + base + row_lo * rstride;
        uint32_t* orow_hi = dst_pk + base + row_hi * rstride;
#pragma unroll
        for (int nt = 0; nt < 8; nt++) {
            const int col = nt * 8 + mcol;
            {
                const float f0 = o[nt][0] * invlo, f1 = o[nt][1] * invlo;
                const uint32_t u0 = __float_as_uint(f0), u1 = __float_as_uint(f1);
                const float l0 = f0 - __uint_as_float(u0 & 0xFFFF0000u);
                const float l1 = f1 - __uint_as_float(u1 & 0xFFFF0000u);
                const uint32_t lop = cvt_bf16x2(l1, l0);
                uint2 w;
                w.x = __byte_perm(u0, lop, 0x5432);
                w.y = __byte_perm(u1, lop, 0x7632);
                *(uint2*)(orow_lo + col) = w;
            }
            {
                const float f0 = o[nt][2] * invhi, f1 = o[nt][3] * invhi;
                const uint32_t u0 = __float_as_uint(f0), u1 = __float_as_uint(f1);
                const float l0 = f0 - __uint_as_float(u0 & 0xFFFF0000u);
                const float l1 = f1 - __uint_as_float(u1 & 0xFFFF0000u);
                const uint32_t lop = cvt_bf16x2(l1, l0);
                uint2 w;
                w.x = __byte_perm(u0, lop, 0x5432);
                w.y = __byte_perm(u1, lop, 0x7632);
                *(uint2*)(orow_hi + col) = w;
            }
        }
    }
}

// ---------------------------------------------------------------------------
extern "C" void kernel_launch(void* const* d_in, const int* in_sizes, int n_in,
                              void* d_out, int out_size)
{
    const float* q    = (const float*)d_in[0];
    const float* k    = (const float*)d_in[1];
    const float* v    = (const float*)d_in[2];
    const float* mask = (const float*)d_in[3];
    float* out = (float*)d_out;

    uint32_t* vt;
    cudaGetSymbolAddress((void**)&vt, g_vt);

    cudaFuncSetAttribute(attn_mma_kernel<false>,
                         cudaFuncAttributeMaxDynamicSharedMemorySize, SM_TOTAL);
    cudaFuncSetAttribute(attn_mma_kernel<true>,
                         cudaFuncAttributeMaxDynamicSharedMemorySize, SM_TOTAL);

    attn_mma_kernel<false><<<Bb * Nn * Hh, 256, SM_TOTAL>>>(
        q, k, v, nullptr, nullptr, vt, nullptr);
    attn_mma_kernel<true><<<Bb * Ll * Hh, 256, SM_TOTAL>>>(
        q, k, nullptr, (const uint32_t*)vt, mask, nullptr, out);
}